// round 14
// baseline (speedup 1.0000x reference)
#include <cuda_runtime.h>
#include <cuda_bf16.h>
#include <cstdint>

// ==================== device scratch (allocation-free) ====================
__device__ __align__(256) float g_y1[4 * 64 * 32 * 32];
__device__ __align__(256) float g_y2c[4 * 64 * 16 * 16];
__device__ __align__(256) float g_y3[4 * 64 * 8 * 8];
__device__ __align__(256) float g_am[4 * 64 * 4096];            // gated input [b][c][hw]
__device__ __align__(256) __nv_bfloat16 g_thb[4 * 4096 * 32];   // theta*log2e bf16 [b][i][c]
__device__ __align__(256) __nv_bfloat16 g_phb[4 * 4096 * 32];   // phi bf16 [b][j][c]
__device__ __align__(256) float g_g[4 * 4096 * 32];             // g fp32 [b][j][c]
__device__ __align__(256) __nv_bfloat16 g_g2t[4 * 32 * 4096];   // g/colsum bf16 [b][c][j]
__device__ __align__(256) float g_y2a[4 * 4096 * 32];           // attn out fp32 [b][i][c]
__device__ __align__(256) float g_probe[4 * 4096];              // probe dead scratch

// ==================== helpers (portable sm_80+ PTX only) ====================
__device__ __forceinline__ uint32_t smem_u32(const void* p) {
    uint32_t a;
    asm("{ .reg .u64 t; cvta.to.shared.u64 t, %1; cvt.u32.u64 %0, t; }" : "=r"(a) : "l"(p));
    return a;
}
__device__ __forceinline__ uint32_t pack_bf16x2(float lo, float hi) {
    uint32_t r;
    asm("cvt.rn.bf16x2.f32 %0, %1, %2;" : "=r"(r) : "f"(hi), "f"(lo));
    return r;
}
__device__ __forceinline__ float ex2f(float x) {
    float r;
    asm("ex2.approx.f32 %0, %1;" : "=f"(r) : "f"(x));
    return r;
}
#define LDM_X4(r0, r1, r2, r3, a) \
    asm volatile("ldmatrix.sync.aligned.m8n8.x4.shared.b16 {%0,%1,%2,%3}, [%4];" \
                 : "=r"(r0), "=r"(r1), "=r"(r2), "=r"(r3) : "r"(a))
#define MMA16816(c0, c1, c2, c3, a0, a1, a2, a3, b0, b1) \
    asm volatile("mma.sync.aligned.m16n8k16.row.col.f32.bf16.bf16.f32 " \
                 "{%0,%1,%2,%3}, {%4,%5,%6,%7}, {%8,%9}, {%0,%1,%2,%3};" \
                 : "+f"(c0), "+f"(c1), "+f"(c2), "+f"(c3) \
                 : "r"(a0), "r"(a1), "r"(a2), "r"(a3), "r"(b0), "r"(b1))
#define CP_ASYNC16(dst, src) \
    asm volatile("cp.async.cg.shared.global [%0], [%1], 16;" :: "r"(dst), "l"(src) : "memory")
#define CP_COMMIT() asm volatile("cp.async.commit_group;" ::: "memory")
#define CP_WAIT1() asm volatile("cp.async.wait_group 1;" ::: "memory")

// ==================== conv3x3 stride2 pad1, C=64 -> C=64 (templated geometry) =========
template <int PX, int NCO>
__global__ void conv3x3_s2(const float* __restrict__ in, float* __restrict__ out,
                           const float* __restrict__ w, const float* __restrict__ bias,
                           int Hin, int Hout, int do_lrelu) {
    __shared__ float ws[16 * 64 * 9];
    const int NT = PX * (64 / NCO);
    int t = threadIdx.x;
    int pxl = t % PX, cog = t / PX;
    int gpx = blockIdx.x * PX + pxl;
    int hw2 = Hout * Hout;
    int b = gpx / hw2;
    int ohw = gpx - b * hw2;
    int oh = ohw / Hout, ow = ohw - oh * Hout;

    float acc[NCO];
#pragma unroll
    for (int c = 0; c < NCO; c++) acc[c] = bias[cog * NCO + c];

    for (int cc = 0; cc < 64; cc += 16) {
        __syncthreads();
        for (int l = t; l < 16 * 64 * 9; l += NT) {
            int ci_l = l / 576;
            int rem = l - ci_l * 576;
            int co = rem / 9;
            int k = rem - co * 9;
            ws[l] = w[(co * 64 + cc + ci_l) * 9 + k];
        }
        __syncthreads();
        for (int ci_l = 0; ci_l < 16; ci_l++) {
            const float* inp = in + (b * 64 + cc + ci_l) * Hin * Hin;
            float v[9];
#pragma unroll
            for (int kh = 0; kh < 3; kh++)
#pragma unroll
                for (int kw = 0; kw < 3; kw++) {
                    int ih = 2 * oh - 1 + kh;
                    int iw = 2 * ow - 1 + kw;
                    bool ok = (ih >= 0) && (ih < Hin) && (iw < Hin) && (iw >= 0);
                    v[kh * 3 + kw] = ok ? inp[ih * Hin + iw] : 0.0f;
                }
            const float* wsp = ws + ci_l * 576 + cog * NCO * 9;
#pragma unroll
            for (int c = 0; c < NCO; c++)
#pragma unroll
                for (int k = 0; k < 9; k++) acc[c] += v[k] * wsp[c * 9 + k];
        }
    }
    float* op = out + b * 64 * hw2 + ohw;
#pragma unroll
    for (int c = 0; c < NCO; c++) {
        float vv = acc[c];
        if (do_lrelu) vv = (vv >= 0.0f) ? vv : 0.2f * vv;
        op[(cog * NCO + c) * hw2] = vv;
    }
}

// ==================== probe: pass1 inner loop, 2 chunks, dead output ====================
// Same grid/block/smem/SASS structure as attn_pass1's mainloop. ncu lands here (kernel idx 3).
__global__ __launch_bounds__(128) void attn_probe(const __nv_bfloat16* __restrict__ thetab,
                                                  const __nv_bfloat16* __restrict__ phib,
                                                  float* __restrict__ probe_out) {
    __shared__ __align__(16) unsigned char sm[25600];
    uint32_t smb = smem_u32(sm);
    const int SPHI = 0, STH0 = 5120, STH1 = 15360;
    int t = threadIdx.x, wid = t >> 5, lane = t & 31;
    int b = blockIdx.y;
    int j0 = blockIdx.x * 64;

#pragma unroll
    for (int v = 0; v < 2; v++) {
        int idx = t + v * 128;
        int row = idx >> 2, c16 = idx & 3;
        float4 d = *(const float4*)((const char*)phib + ((size_t)((b << 12) + j0 + row)) * 64 + c16 * 16);
        *(float4*)(sm + SPHI + row * 80 + c16 * 16) = d;
    }
    __syncthreads();

    uint32_t af[2][4];
#pragma unroll
    for (int kt = 0; kt < 2; kt++) {
        uint32_t a = smb + SPHI + (wid * 16 + (lane & 15)) * 80 + kt * 32 + (lane >> 4) * 16;
        LDM_X4(af[kt][0], af[kt][1], af[kt][2], af[kt][3], a);
    }

    auto load_th = [&](uint32_t soff, int chunk) {
#pragma unroll
        for (int v = 0; v < 4; v++) {
            int idx = t + v * 128;
            int row = idx >> 2, c16 = idx & 3;
            const char* src = (const char*)thetab + ((size_t)((b << 12) + chunk * 128 + row)) * 64 + c16 * 16;
            CP_ASYNC16(smb + soff + row * 80 + c16 * 16, src);
        }
        CP_COMMIT();
    };
    load_th(STH0, 0);
    load_th(STH1, 1);

    float cs0 = 0.0f, cs1 = 0.0f, cs2 = 0.0f, cs3 = 0.0f;
    for (int chunk = 0; chunk < 2; chunk++) {
        uint32_t soff = (chunk & 1) ? STH1 : STH0;
        CP_WAIT1();
        __syncthreads();
        float cr[16][4];
#pragma unroll
        for (int nt = 0; nt < 16; nt++) {
            uint32_t b0, b1, b2, b3;
            LDM_X4(b0, b1, b2, b3, smb + soff + (nt * 8 + (lane & 7)) * 80 + (lane >> 3) * 16);
            cr[nt][0] = 0.0f; cr[nt][1] = 0.0f; cr[nt][2] = 0.0f; cr[nt][3] = 0.0f;
            MMA16816(cr[nt][0], cr[nt][1], cr[nt][2], cr[nt][3],
                     af[0][0], af[0][1], af[0][2], af[0][3], b0, b1);
            MMA16816(cr[nt][0], cr[nt][1], cr[nt][2], cr[nt][3],
                     af[1][0], af[1][1], af[1][2], af[1][3], b2, b3);
        }
#pragma unroll
        for (int nt = 0; nt < 16; nt++) {
            cs0 += ex2f(cr[nt][0]);
            cs1 += ex2f(cr[nt][1]);
            cs2 += ex2f(cr[nt][2]);
            cs3 += ex2f(cr[nt][3]);
        }
        __syncthreads();
        CP_COMMIT();
    }

    float csA = cs0 + cs1 + cs2 + cs3;
    csA += __shfl_xor_sync(0xFFFFFFFF, csA, 1);
    csA += __shfl_xor_sync(0xFFFFFFFF, csA, 2);
    if ((lane & 3) == 0)
        probe_out[(b << 12) + j0 + wid * 16 + (lane >> 2)] = csA;
}

// ==================== amproj v2: 64 px/CTA, grid 256, 384 thr =========================
__global__ __launch_bounds__(384) void amproj(
    const float* __restrict__ y3, const float* __restrict__ x,
    const float* __restrict__ thw, const float* __restrict__ thb,
    const float* __restrict__ phw, const float* __restrict__ phb,
    const float* __restrict__ gw, const float* __restrict__ gb,
    float* __restrict__ am, __nv_bfloat16* __restrict__ thetab,
    __nv_bfloat16* __restrict__ phib, float* __restrict__ gx) {
    __shared__ float wst[3 * 64 * 32];   // [o][ci][c]
    __shared__ float ams[64 * 65];       // [px][ci] stride 65
    __shared__ float bss[96];
    int t = threadIdx.x;
    for (int l = t; l < 6144; l += 384) {
        int o = l / 2048;
        int r = l - o * 2048;
        int c = r >> 6, ci = r & 63;
        const float* src = (o == 0) ? thw : ((o == 1) ? phw : gw);
        wst[o * 2048 + ci * 32 + c] = src[c * 64 + ci];
    }
    if (t < 96) {
        int o = t / 32, c = t & 31;
        const float* src = (o == 0) ? thb : ((o == 1) ? phb : gb);
        bss[o * 32 + c] = src[c];
    }
    int pxBase = blockIdx.x * 64;
    int b = pxBase >> 12;
    int pix0 = pxBase & 4095;
    for (int l = t; l < 4096; l += 384) {
        int ci = l >> 6, px = l & 63;
        int pix = pix0 + px;
        int h = pix >> 6, w = pix & 63;
        float sh = (h + 0.5f) * 0.125f - 0.5f;
        float sw = (w + 0.5f) * 0.125f - 0.5f;
        int h0 = (int)floorf(sh);
        int w0 = (int)floorf(sw);
        float fh = sh - (float)h0;
        float fw = sw - (float)w0;
        int h0c = min(max(h0, 0), 7), h1c = min(max(h0 + 1, 0), 7);
        int w0c = min(max(w0, 0), 7), w1c = min(max(w0 + 1, 0), 7);
        const float* yp = y3 + (b * 64 + ci) * 64;
        float v = (1.0f - fh) * ((1.0f - fw) * yp[h0c * 8 + w0c] + fw * yp[h0c * 8 + w1c]) +
                  fh * ((1.0f - fw) * yp[h1c * 8 + w0c] + fw * yp[h1c * 8 + w1c]);
        float s = 1.0f / (1.0f + __expf(-v));
        float a = s * x[(size_t)(b * 64 + ci) * 4096 + pix];
        ams[px * 65 + ci] = a;
        am[(size_t)(b * 64 + ci) * 4096 + pix] = a;
    }
    __syncthreads();
    int o = t / 128;
    int r = t - o * 128;
    int px = r >> 1, chalf = r & 1;
    const float* wso = wst + o * 2048 + chalf * 16;
    float acc[16];
#pragma unroll
    for (int c = 0; c < 16; c++) acc[c] = bss[o * 32 + chalf * 16 + c];
    const float* ap = ams + px * 65;
#pragma unroll 8
    for (int ci = 0; ci < 64; ci++) {
        float a = ap[ci];
        const float* wrow = wso + ci * 32;
#pragma unroll
        for (int c = 0; c < 16; c++) acc[c] += a * wrow[c];
    }
    size_t gi = (size_t)(pxBase + px);
    if (o == 0) {
        uint32_t* outp = (uint32_t*)thetab + gi * 16 + chalf * 8;
#pragma unroll
        for (int p = 0; p < 8; p++)
            outp[p] = pack_bf16x2(acc[2 * p] * 1.4426950408889634f,
                                  acc[2 * p + 1] * 1.4426950408889634f);
    } else if (o == 1) {
        uint32_t* outp = (uint32_t*)phib + gi * 16 + chalf * 8;
#pragma unroll
        for (int p = 0; p < 8; p++) outp[p] = pack_bf16x2(acc[2 * p], acc[2 * p + 1]);
    } else {
        float* outp = gx + gi * 32 + chalf * 16;
#pragma unroll
        for (int p = 0; p < 4; p++)
            *(float4*)(outp + p * 4) = make_float4(acc[4 * p], acc[4 * p + 1], acc[4 * p + 2], acc[4 * p + 3]);
    }
}

// ==================== pass1 (phase-split): colsum over i for 64 j cols; g2t tail ========
__global__ __launch_bounds__(128) void attn_pass1(const __nv_bfloat16* __restrict__ thetab,
                                                  const __nv_bfloat16* __restrict__ phib,
                                                  const float* __restrict__ g,
                                                  __nv_bfloat16* __restrict__ g2t) {
    __shared__ __align__(16) unsigned char sm[25856];
    uint32_t smb = smem_u32(sm);
    const int SPHI = 0, STH0 = 5120, STH1 = 15360, SINV = 25600;
    int t = threadIdx.x, wid = t >> 5, lane = t & 31;
    int b = blockIdx.y;
    int j0 = blockIdx.x * 64;

#pragma unroll
    for (int v = 0; v < 2; v++) {
        int idx = t + v * 128;
        int row = idx >> 2, c16 = idx & 3;
        float4 d = *(const float4*)((const char*)phib + ((size_t)((b << 12) + j0 + row)) * 64 + c16 * 16);
        *(float4*)(sm + SPHI + row * 80 + c16 * 16) = d;
    }
    __syncthreads();

    uint32_t af[2][4];
#pragma unroll
    for (int kt = 0; kt < 2; kt++) {
        uint32_t a = smb + SPHI + (wid * 16 + (lane & 15)) * 80 + kt * 32 + (lane >> 4) * 16;
        LDM_X4(af[kt][0], af[kt][1], af[kt][2], af[kt][3], a);
    }

    auto load_th = [&](uint32_t soff, int chunk) {
#pragma unroll
        for (int v = 0; v < 4; v++) {
            int idx = t + v * 128;
            int row = idx >> 2, c16 = idx & 3;
            const char* src = (const char*)thetab + ((size_t)((b << 12) + chunk * 128 + row)) * 64 + c16 * 16;
            CP_ASYNC16(smb + soff + row * 80 + c16 * 16, src);
        }
        CP_COMMIT();
    };
    load_th(STH0, 0);
    load_th(STH1, 1);

    float cs0 = 0.0f, cs1 = 0.0f, cs2 = 0.0f, cs3 = 0.0f;
    for (int chunk = 0; chunk < 32; chunk++) {
        uint32_t soff = (chunk & 1) ? STH1 : STH0;
        CP_WAIT1();
        __syncthreads();
        float cr[16][4];
#pragma unroll
        for (int nt = 0; nt < 16; nt++) {
            uint32_t b0, b1, b2, b3;
            LDM_X4(b0, b1, b2, b3, smb + soff + (nt * 8 + (lane & 7)) * 80 + (lane >> 3) * 16);
            cr[nt][0] = 0.0f; cr[nt][1] = 0.0f; cr[nt][2] = 0.0f; cr[nt][3] = 0.0f;
            MMA16816(cr[nt][0], cr[nt][1], cr[nt][2], cr[nt][3],
                     af[0][0], af[0][1], af[0][2], af[0][3], b0, b1);
            MMA16816(cr[nt][0], cr[nt][1], cr[nt][2], cr[nt][3],
                     af[1][0], af[1][1], af[1][2], af[1][3], b2, b3);
        }
#pragma unroll
        for (int nt = 0; nt < 16; nt++) {
            cs0 += ex2f(cr[nt][0]);
            cs1 += ex2f(cr[nt][1]);
            cs2 += ex2f(cr[nt][2]);
            cs3 += ex2f(cr[nt][3]);
        }
        __syncthreads();
        if (chunk + 2 < 32) load_th(soff, chunk + 2);
        else CP_COMMIT();
    }

    float csA = cs0 + cs1, csB = cs2 + cs3;
    csA += __shfl_xor_sync(0xFFFFFFFF, csA, 1);
    csA += __shfl_xor_sync(0xFFFFFFFF, csA, 2);
    csB += __shfl_xor_sync(0xFFFFFFFF, csB, 1);
    csB += __shfl_xor_sync(0xFFFFFFFF, csB, 2);
    float* sinv = (float*)(sm + SINV);
    if ((lane & 3) == 0) {
        sinv[wid * 16 + (lane >> 2)] = 1.0f / csA;
        sinv[wid * 16 + 8 + (lane >> 2)] = 1.0f / csB;
    }
    __syncthreads();

    __nv_bfloat16* sgt = (__nv_bfloat16*)(sm + SPHI);
    {
        int r = t >> 1, half = t & 1;
        const float* gp = g + ((size_t)((b << 12) + j0 + r)) * 32 + half * 16;
        float inv = sinv[r];
#pragma unroll
        for (int c = 0; c < 16; c++)
            sgt[(half * 16 + c) * 72 + r] = __float2bfloat16(gp[c] * inv);
    }
    __syncthreads();
#pragma unroll
    for (int v = 0; v < 2; v++) {
        int idx = t + v * 128;
        int c = idx >> 3, m = idx & 7;
        uint4 d = *(const uint4*)((const char*)sgt + c * 144 + m * 16);
        *(uint4*)((char*)g2t + (((size_t)(b * 32 + c)) * 4096 + (size_t)j0) * 2 + m * 16) = d;
    }
}

// ==================== pass2 (phase-split): y2[i,c] = sum_j exp2(f') * g2t ==============
__global__ __launch_bounds__(128) void attn_pass2(const __nv_bfloat16* __restrict__ thetab,
                                                  const __nv_bfloat16* __restrict__ phib,
                                                  const __nv_bfloat16* __restrict__ g2t,
                                                  float* __restrict__ y2) {
    __shared__ __align__(16) unsigned char sm[43008];
    uint32_t smb = smem_u32(sm);
    const int STH = 0, SPHI0 = 5120, SPHI1 = 15360, SG0 = 25600, SG1 = 34304;
    int t = threadIdx.x, wid = t >> 5, lane = t & 31;
    int b = blockIdx.y;
    int i0 = blockIdx.x * 64;

#pragma unroll
    for (int v = 0; v < 2; v++) {
        int idx = t + v * 128;
        int row = idx >> 2, c16 = idx & 3;
        float4 d = *(const float4*)((const char*)thetab + ((size_t)((b << 12) + i0 + row)) * 64 + c16 * 16);
        *(float4*)(sm + STH + row * 80 + c16 * 16) = d;
    }
    __syncthreads();

    uint32_t af[2][4];
#pragma unroll
    for (int kt = 0; kt < 2; kt++) {
        uint32_t a = smb + STH + (wid * 16 + (lane & 15)) * 80 + kt * 32 + (lane >> 4) * 16;
        LDM_X4(af[kt][0], af[kt][1], af[kt][2], af[kt][3], a);
    }

    auto load_chunk = [&](uint32_t sphi, uint32_t sg, int chunk) {
#pragma unroll
        for (int v = 0; v < 4; v++) {
            int idx = t + v * 128;
            int row = idx >> 2, c16 = idx & 3;
            const char* src = (const char*)phib + ((size_t)((b << 12) + chunk * 128 + row)) * 64 + c16 * 16;
            CP_ASYNC16(smb + sphi + row * 80 + c16 * 16, src);
        }
#pragma unroll
        for (int v = 0; v < 4; v++) {
            int idx = t + v * 128;
            int row = idx >> 4, m = idx & 15;
            const char* src = (const char*)g2t + (((size_t)(b * 32 + row)) * 4096 + (size_t)(chunk * 128)) * 2 + m * 16;
            CP_ASYNC16(smb + sg + row * 272 + m * 16, src);
        }
        CP_COMMIT();
    };
    load_chunk(SPHI0, SG0, 0);
    load_chunk(SPHI1, SG1, 1);

    float y2acc[4][4];
#pragma unroll
    for (int cn = 0; cn < 4; cn++)
#pragma unroll
        for (int r = 0; r < 4; r++) y2acc[cn][r] = 0.0f;

    for (int chunk = 0; chunk < 32; chunk++) {
        uint32_t sphi = (chunk & 1) ? SPHI1 : SPHI0;
        uint32_t sg = (chunk & 1) ? SG1 : SG0;
        CP_WAIT1();
        __syncthreads();
        float cr[8][2][4];
#pragma unroll
        for (int p = 0; p < 8; p++) {
#pragma unroll
            for (int half = 0; half < 2; half++) {
                uint32_t b0, b1, b2, b3;
                LDM_X4(b0, b1, b2, b3,
                       smb + sphi + ((2 * p + half) * 8 + (lane & 7)) * 80 + (lane >> 3) * 16);
                cr[p][half][0] = 0.0f; cr[p][half][1] = 0.0f;
                cr[p][half][2] = 0.0f; cr[p][half][3] = 0.0f;
                MMA16816(cr[p][half][0], cr[p][half][1], cr[p][half][2], cr[p][half][3],
                         af[0][0], af[0][1], af[0][2], af[0][3], b0, b1);
                MMA16816(cr[p][half][0], cr[p][half][1], cr[p][half][2], cr[p][half][3],
                         af[1][0], af[1][1], af[1][2], af[1][3], b2, b3);
            }
        }
        uint32_t pa[8][4];
#pragma unroll
        for (int p = 0; p < 8; p++) {
            pa[p][0] = pack_bf16x2(ex2f(cr[p][0][0]), ex2f(cr[p][0][1]));
            pa[p][1] = pack_bf16x2(ex2f(cr[p][0][2]), ex2f(cr[p][0][3]));
            pa[p][2] = pack_bf16x2(ex2f(cr[p][1][0]), ex2f(cr[p][1][1]));
            pa[p][3] = pack_bf16x2(ex2f(cr[p][1][2]), ex2f(cr[p][1][3]));
        }
#pragma unroll
        for (int p = 0; p < 8; p++) {
#pragma unroll
            for (int pr = 0; pr < 2; pr++) {
                uint32_t u0, u1, u2, u3;
                LDM_X4(u0, u1, u2, u3,
                       smb + sg + ((pr * 2 + (lane >> 4)) * 8 + (lane & 7)) * 272 + p * 32 + ((lane >> 3) & 1) * 16);
                MMA16816(y2acc[pr * 2][0], y2acc[pr * 2][1], y2acc[pr * 2][2], y2acc[pr * 2][3],
                         pa[p][0], pa[p][1], pa[p][2], pa[p][3], u0, u1);
                MMA16816(y2acc[pr * 2 + 1][0], y2acc[pr * 2 + 1][1], y2acc[pr * 2 + 1][2], y2acc[pr * 2 + 1][3],
                         pa[p][0], pa[p][1], pa[p][2], pa[p][3], u2, u3);
            }
        }
        __syncthreads();
        if (chunk + 2 < 32) load_chunk(sphi, sg, chunk + 2);
        else CP_COMMIT();
    }

    int q = lane & 3, gq = lane >> 2;
#pragma unroll
    for (int cn = 0; cn < 4; cn++) {
        int col = cn * 8 + q * 2;
        size_t r0 = ((size_t)((b << 12) + i0 + wid * 16 + gq)) * 32;
        size_t r1 = ((size_t)((b << 12) + i0 + wid * 16 + gq + 8)) * 32;
        *(float2*)&y2[r0 + col] = make_float2(y2acc[cn][0], y2acc[cn][1]);
        *(float2*)&y2[r1 + col] = make_float2(y2acc[cn][2], y2acc[cn][3]);
    }
}

// ==================== epilogue: out = (W@y2 + wb + am) * x ====================
__global__ void epilogue(const float* __restrict__ y2, const float* __restrict__ ww,
                         const float* __restrict__ wb, const float* __restrict__ am,
                         const float* __restrict__ x, float* __restrict__ out) {
    __shared__ float sy[64 * 33];
    __shared__ float sw[64 * 32];
    __shared__ float sb[64];
    int t = threadIdx.x;
    for (int l = t; l < 2048; l += 256) sw[l] = ww[l];
    if (t < 64) sb[t] = wb[t];
    int pxBase = blockIdx.x * 64;
    for (int l = t; l < 2048; l += 256) {
        int p = l >> 5, c = l & 31;
        sy[p * 33 + c] = y2[(size_t)(pxBase + p) * 32 + c];
    }
    __syncthreads();
    int px = t & 63, cog = t >> 6;
    int b = pxBase >> 12;
    int pix = (pxBase & 4095) + px;
#pragma unroll
    for (int c16 = 0; c16 < 16; c16++) {
        int co = cog * 16 + c16;
        float a = sb[co];
#pragma unroll
        for (int c = 0; c < 32; c++) a += sw[co * 32 + c] * sy[px * 33 + c];
        int oidx = (b * 64 + co) * 4096 + pix;
        out[oidx] = (a + am[oidx]) * x[oidx];
    }
}

// ==================== launch ====================
extern "C" void kernel_launch(void* const* d_in, const int* in_sizes, int n_in,
                              void* d_out, int out_size) {
    (void)in_sizes; (void)n_in; (void)out_size;
    const float* x = (const float*)d_in[0];
    const float* d1w = (const float*)d_in[1];
    const float* d1b = (const float*)d_in[2];
    const float* d2w = (const float*)d_in[3];
    const float* d2b = (const float*)d_in[4];
    const float* d3w = (const float*)d_in[5];
    const float* d3b = (const float*)d_in[6];
    const float* gw = (const float*)d_in[7];
    const float* gb = (const float*)d_in[8];
    const float* thw = (const float*)d_in[9];
    const float* thb = (const float*)d_in[10];
    const float* phw = (const float*)d_in[11];
    const float* phb = (const float*)d_in[12];
    const float* www = (const float*)d_in[13];
    const float* wwb = (const float*)d_in[14];
    float* out = (float*)d_out;

    float *p_y1, *p_y2c, *p_y3, *p_am, *p_g, *p_y2a, *p_probe;
    __nv_bfloat16 *p_th, *p_ph, *p_g2t;
    cudaGetSymbolAddress((void**)&p_y1, g_y1);
    cudaGetSymbolAddress((void**)&p_y2c, g_y2c);
    cudaGetSymbolAddress((void**)&p_y3, g_y3);
    cudaGetSymbolAddress((void**)&p_am, g_am);
    cudaGetSymbolAddress((void**)&p_th, g_thb);
    cudaGetSymbolAddress((void**)&p_ph, g_phb);
    cudaGetSymbolAddress((void**)&p_g, g_g);
    cudaGetSymbolAddress((void**)&p_g2t, g_g2t);
    cudaGetSymbolAddress((void**)&p_y2a, g_y2a);
    cudaGetSymbolAddress((void**)&p_probe, g_probe);

    // kernel idx:            0      1      2      3(profiled) 4       5      6      7
    conv3x3_s2<32, 8><<<128, 256>>>(x, p_y1, d1w, d1b, 64, 32, 1);
    conv3x3_s2<16, 4><<<64, 256>>>(p_y1, p_y2c, d2w, d2b, 32, 16, 1);
    conv3x3_s2<8, 2><<<32, 256>>>(p_y2c, p_y3, d3w, d3b, 16, 8, 0);
    attn_probe<<<dim3(64, 4), 128>>>(p_th, p_ph, p_probe);  // reads prev-replay theta/phi; dead output
    amproj<<<256, 384>>>(p_y3, x, thw, thb, phw, phb, gw, gb, p_am, p_th, p_ph, p_g);
    attn_pass1<<<dim3(64, 4), 128>>>(p_th, p_ph, p_g, p_g2t);
    attn_pass2<<<dim3(64, 4), 128>>>(p_th, p_ph, p_g2t, p_y2a);
    epilogue<<<256, 256>>>(p_y2a, www, wwb, p_am, x, out);
}

// round 16
// speedup vs baseline: 1.0673x; 1.0673x over previous
#include <cuda_runtime.h>
#include <cuda_fp16.h>
#include <cstdint>

// ==================== device scratch (allocation-free) ====================
__device__ __align__(256) float g_y1[4 * 64 * 32 * 32];
__device__ __align__(256) float g_y2c[4 * 64 * 16 * 16];
__device__ __align__(256) float g_y3[4 * 64 * 8 * 8];
__device__ __align__(256) float g_am[4 * 64 * 4096];       // gated input [b][c][hw]
__device__ __align__(256) __half g_thh[4 * 4096 * 32];     // theta*log2e fp16 [b][i][c]
__device__ __align__(256) __half g_phh[4 * 4096 * 32];     // phi fp16 [b][j][c]
__device__ __align__(256) float g_g[4 * 4096 * 32];        // g fp32 [b][j][c]
__device__ __align__(256) __half g_g2t[4 * 32 * 4096];     // g/colsum fp16 [b][c][j]
__device__ __align__(256) float g_y2a[4 * 4096 * 32];      // attn out fp32 [b][i][c]

// ==================== helpers (portable sm_80+ PTX only) ====================
__device__ __forceinline__ uint32_t smem_u32(const void* p) {
    uint32_t a;
    asm("{ .reg .u64 t; cvta.to.shared.u64 t, %1; cvt.u32.u64 %0, t; }" : "=r"(a) : "l"(p));
    return a;
}
__device__ __forceinline__ uint32_t pack_f16x2(float lo, float hi) {
    uint32_t r;
    asm("cvt.rn.f16x2.f32 %0, %1, %2;" : "=r"(r) : "f"(hi), "f"(lo));
    return r;
}
__device__ __forceinline__ uint32_t hex2(uint32_t x) {  // ex2 on packed f16x2
    uint32_t r;
    asm("ex2.approx.f16x2 %0, %1;" : "=r"(r) : "r"(x));
    return r;
}
__device__ __forceinline__ uint32_t hadd2(uint32_t a, uint32_t b) {
    uint32_t r;
    asm("add.f16x2 %0, %1, %2;" : "=r"(r) : "r"(a), "r"(b));
    return r;
}
__device__ __forceinline__ float2 h22f2(uint32_t h) {
    __half2 v = *reinterpret_cast<__half2*>(&h);
    return __half22float2(v);
}
#define LDM_X4(r0, r1, r2, r3, a) \
    asm volatile("ldmatrix.sync.aligned.m8n8.x4.shared.b16 {%0,%1,%2,%3}, [%4];" \
                 : "=r"(r0), "=r"(r1), "=r"(r2), "=r"(r3) : "r"(a))
// f16-accumulator HMMA: D,C are 2 packed f16x2 regs
#define MMA16816H(c0, c1, a0, a1, a2, a3, b0, b1) \
    asm volatile("mma.sync.aligned.m16n8k16.row.col.f16.f16.f16.f16 " \
                 "{%0,%1}, {%2,%3,%4,%5}, {%6,%7}, {%0,%1};" \
                 : "+r"(c0), "+r"(c1) \
                 : "r"(a0), "r"(a1), "r"(a2), "r"(a3), "r"(b0), "r"(b1))
#define CP_ASYNC16(dst, src) \
    asm volatile("cp.async.cg.shared.global [%0], [%1], 16;" :: "r"(dst), "l"(src) : "memory")
#define CP_COMMIT() asm volatile("cp.async.commit_group;" ::: "memory")
#define CP_WAIT1() asm volatile("cp.async.wait_group 1;" ::: "memory")

// ==================== conv3x3 stride2 pad1, C=64 -> C=64 (templated geometry) =========
template <int PX, int NCO>
__global__ void conv3x3_s2(const float* __restrict__ in, float* __restrict__ out,
                           const float* __restrict__ w, const float* __restrict__ bias,
                           int Hin, int Hout, int do_lrelu) {
    __shared__ float ws[16 * 64 * 9];
    const int NT = PX * (64 / NCO);
    int t = threadIdx.x;
    int pxl = t % PX, cog = t / PX;
    int gpx = blockIdx.x * PX + pxl;
    int hw2 = Hout * Hout;
    int b = gpx / hw2;
    int ohw = gpx - b * hw2;
    int oh = ohw / Hout, ow = ohw - oh * Hout;

    float acc[NCO];
#pragma unroll
    for (int c = 0; c < NCO; c++) acc[c] = bias[cog * NCO + c];

    for (int cc = 0; cc < 64; cc += 16) {
        __syncthreads();
        for (int l = t; l < 16 * 64 * 9; l += NT) {
            int ci_l = l / 576;
            int rem = l - ci_l * 576;
            int co = rem / 9;
            int k = rem - co * 9;
            ws[l] = w[(co * 64 + cc + ci_l) * 9 + k];
        }
        __syncthreads();
        for (int ci_l = 0; ci_l < 16; ci_l++) {
            const float* inp = in + (b * 64 + cc + ci_l) * Hin * Hin;
            float v[9];
#pragma unroll
            for (int kh = 0; kh < 3; kh++)
#pragma unroll
                for (int kw = 0; kw < 3; kw++) {
                    int ih = 2 * oh - 1 + kh;
                    int iw = 2 * ow - 1 + kw;
                    bool ok = (ih >= 0) && (ih < Hin) && (iw >= 0) && (iw < Hin);
                    v[kh * 3 + kw] = ok ? inp[ih * Hin + iw] : 0.0f;
                }
            const float* wsp = ws + ci_l * 576 + cog * NCO * 9;
#pragma unroll
            for (int c = 0; c < NCO; c++)
#pragma unroll
                for (int k = 0; k < 9; k++) acc[c] += v[k] * wsp[c * 9 + k];
        }
    }
    float* op = out + b * 64 * hw2 + ohw;
#pragma unroll
    for (int c = 0; c < NCO; c++) {
        float vv = acc[c];
        if (do_lrelu) vv = (vv >= 0.0f) ? vv : 0.2f * vv;
        op[(cog * NCO + c) * hw2] = vv;
    }
}

// ==================== amproj: fused upsample+gate + three 1x1 projections ==============
__global__ __launch_bounds__(384) void amproj(
    const float* __restrict__ y3, const float* __restrict__ x,
    const float* __restrict__ thw, const float* __restrict__ thb,
    const float* __restrict__ phw, const float* __restrict__ phb,
    const float* __restrict__ gw, const float* __restrict__ gb,
    float* __restrict__ am, __half* __restrict__ thetah,
    __half* __restrict__ phih, float* __restrict__ gx) {
    __shared__ float wst[3 * 64 * 32];   // [o][ci][c]
    __shared__ float ams[64 * 65];       // [px][ci] stride 65
    __shared__ float bss[96];
    int t = threadIdx.x;
    for (int l = t; l < 6144; l += 384) {
        int o = l / 2048;
        int r = l - o * 2048;
        int c = r >> 6, ci = r & 63;
        const float* src = (o == 0) ? thw : ((o == 1) ? phw : gw);
        wst[o * 2048 + ci * 32 + c] = src[c * 64 + ci];
    }
    if (t < 96) {
        int o = t / 32, c = t & 31;
        const float* src = (o == 0) ? thb : ((o == 1) ? phb : gb);
        bss[o * 32 + c] = src[c];
    }
    int pxBase = blockIdx.x * 64;
    int b = pxBase >> 12;
    int pix0 = pxBase & 4095;
    for (int l = t; l < 4096; l += 384) {
        int ci = l >> 6, px = l & 63;
        int pix = pix0 + px;
        int h = pix >> 6, w = pix & 63;
        float sh = (h + 0.5f) * 0.125f - 0.5f;
        float sw = (w + 0.5f) * 0.125f - 0.5f;
        int h0 = (int)floorf(sh);
        int w0 = (int)floorf(sw);
        float fh = sh - (float)h0;
        float fw = sw - (float)w0;
        int h0c = min(max(h0, 0), 7), h1c = min(max(h0 + 1, 0), 7);
        int w0c = min(max(w0, 0), 7), w1c = min(max(w0 + 1, 0), 7);
        const float* yp = y3 + (b * 64 + ci) * 64;
        float v = (1.0f - fh) * ((1.0f - fw) * yp[h0c * 8 + w0c] + fw * yp[h0c * 8 + w1c]) +
                  fh * ((1.0f - fw) * yp[h1c * 8 + w0c] + fw * yp[h1c * 8 + w1c]);
        float s = 1.0f / (1.0f + __expf(-v));
        float a = s * x[(size_t)(b * 64 + ci) * 4096 + pix];
        ams[px * 65 + ci] = a;
        am[(size_t)(b * 64 + ci) * 4096 + pix] = a;
    }
    __syncthreads();
    int o = t / 128;
    int r = t - o * 128;
    int px = r >> 1, chalf = r & 1;
    const float* wso = wst + o * 2048 + chalf * 16;
    float acc[16];
#pragma unroll
    for (int c = 0; c < 16; c++) acc[c] = bss[o * 32 + chalf * 16 + c];
    const float* ap = ams + px * 65;
#pragma unroll 8
    for (int ci = 0; ci < 64; ci++) {
        float a = ap[ci];
        const float* wrow = wso + ci * 32;
#pragma unroll
        for (int c = 0; c < 16; c++) acc[c] += a * wrow[c];
    }
    size_t gi = (size_t)(pxBase + px);
    if (o == 0) {
        uint32_t* outp = (uint32_t*)thetah + gi * 16 + chalf * 8;
#pragma unroll
        for (int p = 0; p < 8; p++)
            outp[p] = pack_f16x2(acc[2 * p] * 1.4426950408889634f,
                                 acc[2 * p + 1] * 1.4426950408889634f);
    } else if (o == 1) {
        uint32_t* outp = (uint32_t*)phih + gi * 16 + chalf * 8;
#pragma unroll
        for (int p = 0; p < 8; p++) outp[p] = pack_f16x2(acc[2 * p], acc[2 * p + 1]);
    } else {
        float* outp = gx + gi * 32 + chalf * 16;
#pragma unroll
        for (int p = 0; p < 4; p++)
            *(float4*)(outp + p * 4) = make_float4(acc[4 * p], acc[4 * p + 1], acc[4 * p + 2], acc[4 * p + 3]);
    }
}

// ==================== pass1 (f16-acc): colsum over i for 64 j cols; g2t tail ===========
// grid (64 jT, 4 b), 128 thr (4 warps x 16 j). 32 chunks of 128 i, 2-stage cp.async.
__global__ __launch_bounds__(128) void attn_pass1(const __half* __restrict__ thetah,
                                                  const __half* __restrict__ phih,
                                                  const float* __restrict__ g,
                                                  __half* __restrict__ g2t) {
    __shared__ __align__(16) unsigned char sm[25856];
    // SPHI[0..5120) STH0[5120..15360) STH1[15360..25600) SINV[25600..25856)
    uint32_t smb = smem_u32(sm);
    const int SPHI = 0, STH0 = 5120, STH1 = 15360, SINV = 25600;
    int t = threadIdx.x, wid = t >> 5, lane = t & 31;
    int b = blockIdx.y;
    int j0 = blockIdx.x * 64;

#pragma unroll
    for (int v = 0; v < 2; v++) {
        int idx = t + v * 128;
        int row = idx >> 2, c16 = idx & 3;
        float4 d = *(const float4*)((const char*)phih + ((size_t)((b << 12) + j0 + row)) * 64 + c16 * 16);
        *(float4*)(sm + SPHI + row * 80 + c16 * 16) = d;
    }
    __syncthreads();

    uint32_t af[2][4];
#pragma unroll
    for (int kt = 0; kt < 2; kt++) {
        uint32_t a = smb + SPHI + (wid * 16 + (lane & 15)) * 80 + kt * 32 + (lane >> 4) * 16;
        LDM_X4(af[kt][0], af[kt][1], af[kt][2], af[kt][3], a);
    }

    auto load_th = [&](uint32_t soff, int chunk) {
#pragma unroll
        for (int v = 0; v < 4; v++) {
            int idx = t + v * 128;
            int row = idx >> 2, c16 = idx & 3;
            const char* src = (const char*)thetah + ((size_t)((b << 12) + chunk * 128 + row)) * 64 + c16 * 16;
            CP_ASYNC16(smb + soff + row * 80 + c16 * 16, src);
        }
        CP_COMMIT();
    };
    load_th(STH0, 0);
    load_th(STH1, 1);

    float csA = 0.0f, csB = 0.0f;
    for (int chunk = 0; chunk < 32; chunk++) {
        uint32_t soff = (chunk & 1) ? STH1 : STH0;
        CP_WAIT1();
        __syncthreads();
        // phase A: all MMAs (f16 acc, packed C), park in registers
        uint32_t cr[16][2];
#pragma unroll
        for (int nt = 0; nt < 16; nt++) {
            uint32_t b0, b1, b2, b3;
            LDM_X4(b0, b1, b2, b3, smb + soff + (nt * 8 + (lane & 7)) * 80 + (lane >> 3) * 16);
            cr[nt][0] = 0; cr[nt][1] = 0;
            MMA16816H(cr[nt][0], cr[nt][1], af[0][0], af[0][1], af[0][2], af[0][3], b0, b1);
            MMA16816H(cr[nt][0], cr[nt][1], af[1][0], af[1][1], af[1][2], af[1][3], b2, b3);
        }
        // phase B: ex2.f16x2 stream + f16x2 pairwise sum, one f32 upconvert per chunk
        uint32_t es0 = 0, es1 = 0;
#pragma unroll
        for (int nt = 0; nt < 16; nt++) {
            es0 = hadd2(es0, hex2(cr[nt][0]));
            es1 = hadd2(es1, hex2(cr[nt][1]));
        }
        float2 f0 = h22f2(es0), f1 = h22f2(es1);
        csA += f0.x + f0.y;
        csB += f1.x + f1.y;
        __syncthreads();
        if (chunk + 2 < 32) load_th(soff, chunk + 2);
        else CP_COMMIT();
    }

    csA += __shfl_xor_sync(0xFFFFFFFF, csA, 1);
    csA += __shfl_xor_sync(0xFFFFFFFF, csA, 2);
    csB += __shfl_xor_sync(0xFFFFFFFF, csB, 1);
    csB += __shfl_xor_sync(0xFFFFFFFF, csB, 2);
    float* sinv = (float*)(sm + SINV);
    if ((lane & 3) == 0) {
        sinv[wid * 16 + (lane >> 2)] = 1.0f / csA;
        sinv[wid * 16 + 8 + (lane >> 2)] = 1.0f / csB;
    }
    __syncthreads();

    // tail: g2t[c][j0..j0+63] = fp16( g[j][c]*inv[j] ); stage [c][j] stride 144B
    __half* sgt = (__half*)(sm + SPHI);
    {
        int r = t >> 1, half = t & 1;
        const float* gp = g + ((size_t)((b << 12) + j0 + r)) * 32 + half * 16;
        float inv = sinv[r];
#pragma unroll
        for (int c = 0; c < 16; c++)
            sgt[(half * 16 + c) * 72 + r] = __float2half(gp[c] * inv);
    }
    __syncthreads();
#pragma unroll
    for (int v = 0; v < 2; v++) {
        int idx = t + v * 128;
        int c = idx >> 3, m = idx & 7;
        uint4 d = *(const uint4*)((const char*)sgt + c * 144 + m * 16);
        *(uint4*)((char*)g2t + (((size_t)(b * 32 + c)) * 4096 + (size_t)j0) * 2 + m * 16) = d;
    }
}

// ==================== pass2 (f16-acc): y2[i,c] = sum_j exp2(f') * g2t ===================
// grid (64 iT, 4 b), 128 thr (4 warps x 16 i). 32 chunks of 128 j, 2-stage.
__global__ __launch_bounds__(128) void attn_pass2(const __half* __restrict__ thetah,
                                                  const __half* __restrict__ phih,
                                                  const __half* __restrict__ g2t,
                                                  float* __restrict__ y2) {
    __shared__ __align__(16) unsigned char sm[43008];
    uint32_t smb = smem_u32(sm);
    const int STH = 0, SPHI0 = 5120, SPHI1 = 15360, SG0 = 25600, SG1 = 34304;
    int t = threadIdx.x, wid = t >> 5, lane = t & 31;
    int b = blockIdx.y;
    int i0 = blockIdx.x * 64;

#pragma unroll
    for (int v = 0; v < 2; v++) {
        int idx = t + v * 128;
        int row = idx >> 2, c16 = idx & 3;
        float4 d = *(const float4*)((const char*)thetah + ((size_t)((b << 12) + i0 + row)) * 64 + c16 * 16);
        *(float4*)(sm + STH + row * 80 + c16 * 16) = d;
    }
    __syncthreads();

    uint32_t af[2][4];
#pragma unroll
    for (int kt = 0; kt < 2; kt++) {
        uint32_t a = smb + STH + (wid * 16 + (lane & 15)) * 80 + kt * 32 + (lane >> 4) * 16;
        LDM_X4(af[kt][0], af[kt][1], af[kt][2], af[kt][3], a);
    }

    auto load_chunk = [&](uint32_t sphi, uint32_t sg, int chunk) {
#pragma unroll
        for (int v = 0; v < 4; v++) {
            int idx = t + v * 128;
            int row = idx >> 2, c16 = idx & 3;
            const char* src = (const char*)phih + ((size_t)((b << 12) + chunk * 128 + row)) * 64 + c16 * 16;
            CP_ASYNC16(smb + sphi + row * 80 + c16 * 16, src);
        }
#pragma unroll
        for (int v = 0; v < 4; v++) {
            int idx = t + v * 128;  // 32 c-rows x 16 chunks of 16B
            int row = idx >> 4, m = idx & 15;
            const char* src = (const char*)g2t + (((size_t)(b * 32 + row)) * 4096 + (size_t)(chunk * 128)) * 2 + m * 16;
            CP_ASYNC16(smb + sg + row * 272 + m * 16, src);
        }
        CP_COMMIT();
    };
    load_chunk(SPHI0, SG0, 0);
    load_chunk(SPHI1, SG1, 1);

    float y2acc[4][4];
#pragma unroll
    for (int cn = 0; cn < 4; cn++)
#pragma unroll
        for (int r = 0; r < 4; r++) y2acc[cn][r] = 0.0f;

    for (int chunk = 0; chunk < 32; chunk++) {
        uint32_t sphi = (chunk & 1) ? SPHI1 : SPHI0;
        uint32_t sg = (chunk & 1) ? SG1 : SG0;
        CP_WAIT1();
        __syncthreads();
        // phase A: 16 QK ntiles (8 p x 2 halves), f16 acc packed
        uint32_t cr[8][2][2];
#pragma unroll
        for (int p = 0; p < 8; p++) {
#pragma unroll
            for (int half = 0; half < 2; half++) {
                uint32_t b0, b1, b2, b3;
                LDM_X4(b0, b1, b2, b3,
                       smb + sphi + ((2 * p + half) * 8 + (lane & 7)) * 80 + (lane >> 3) * 16);
                cr[p][half][0] = 0; cr[p][half][1] = 0;
                MMA16816H(cr[p][half][0], cr[p][half][1],
                          af[0][0], af[0][1], af[0][2], af[0][3], b0, b1);
                MMA16816H(cr[p][half][0], cr[p][half][1],
                          af[1][0], af[1][1], af[1][2], af[1][3], b2, b3);
            }
        }
        // phase B: in-place ex2.f16x2 — C regs become PV A fragments directly
#pragma unroll
        for (int p = 0; p < 8; p++) {
            cr[p][0][0] = hex2(cr[p][0][0]);
            cr[p][0][1] = hex2(cr[p][0][1]);
            cr[p][1][0] = hex2(cr[p][1][0]);
            cr[p][1][1] = hex2(cr[p][1][1]);
        }
        // phase C: PV MMAs, f16 acc per chunk
        uint32_t y2h[4][2];
#pragma unroll
        for (int cn = 0; cn < 4; cn++) { y2h[cn][0] = 0; y2h[cn][1] = 0; }
#pragma unroll
        for (int p = 0; p < 8; p++) {
#pragma unroll
            for (int pr = 0; pr < 2; pr++) {
                uint32_t u0, u1, u2, u3;
                LDM_X4(u0, u1, u2, u3,
                       smb + sg + ((pr * 2 + (lane >> 4)) * 8 + (lane & 7)) * 272 + p * 32 + ((lane >> 3) & 1) * 16);
                MMA16816H(y2h[pr * 2][0], y2h[pr * 2][1],
                          cr[p][0][0], cr[p][0][1], cr[p][1][0], cr[p][1][1], u0, u1);
                MMA16816H(y2h[pr * 2 + 1][0], y2h[pr * 2 + 1][1],
                          cr[p][0][0], cr[p][0][1], cr[p][1][0], cr[p][1][1], u2, u3);
            }
        }
        // upconvert chunk partials to f32 accumulators
#pragma unroll
        for (int cn = 0; cn < 4; cn++) {
            float2 f0 = h22f2(y2h[cn][0]);
            float2 f1 = h22f2(y2h[cn][1]);
            y2acc[cn][0] += f0.x;
            y2acc[cn][1] += f0.y;
            y2acc[cn][2] += f1.x;
            y2acc[cn][3] += f1.y;
        }
        __syncthreads();
        if (chunk + 2 < 32) load_chunk(sphi, sg, chunk + 2);
        else CP_COMMIT();
    }

    int q = lane & 3, gq = lane >> 2;
#pragma unroll
    for (int cn = 0; cn < 4; cn++) {
        int col = cn * 8 + q * 2;
        size_t r0 = ((size_t)((b << 12) + i0 + wid * 16 + gq)) * 32;
        size_t r1 = ((size_t)((b << 12) + i0 + wid * 16 + gq + 8)) * 32;
        *(float2*)&y2[r0 + col] = make_float2(y2acc[cn][0], y2acc[cn][1]);
        *(float2*)&y2[r1 + col] = make_float2(y2acc[cn][2], y2acc[cn][3]);
    }
}

// ==================== epilogue: out = (W@y2 + wb + am) * x ====================
__global__ void epilogue(const float* __restrict__ y2, const float* __restrict__ ww,
                         const float* __restrict__ wb, const float* __restrict__ am,
                         const float* __restrict__ x, float* __restrict__ out) {
    __shared__ float sy[64 * 33];
    __shared__ float sw[64 * 32];
    __shared__ float sb[64];
    int t = threadIdx.x;
    for (int l = t; l < 2048; l += 256) sw[l] = ww[l];
    if (t < 64) sb[t] = wb[t];
    int pxBase = blockIdx.x * 64;
    for (int l = t; l < 2048; l += 256) {
        int p = l >> 5, c = l & 31;
        sy[p * 33 + c] = y2[(size_t)(pxBase + p) * 32 + c];
    }
    __syncthreads();
    int px = t & 63, cog = t >> 6;
    int b = pxBase >> 12;
    int pix = (pxBase & 4095) + px;
#pragma unroll
    for (int c16 = 0; c16 < 16; c16++) {
        int co = cog * 16 + c16;
        float a = sb[co];
#pragma unroll
        for (int c = 0; c < 32; c++) a += sw[co * 32 + c] * sy[px * 33 + c];
        int oidx = (b * 64 + co) * 4096 + pix;
        out[oidx] = (a + am[oidx]) * x[oidx];
    }
}

// ==================== launch ====================
extern "C" void kernel_launch(void* const* d_in, const int* in_sizes, int n_in,
                              void* d_out, int out_size) {
    (void)in_sizes; (void)n_in; (void)out_size;
    const float* x = (const float*)d_in[0];
    const float* d1w = (const float*)d_in[1];
    const float* d1b = (const float*)d_in[2];
    const float* d2w = (const float*)d_in[3];
    const float* d2b = (const float*)d_in[4];
    const float* d3w = (const float*)d_in[5];
    const float* d3b = (const float*)d_in[6];
    const float* gw = (const float*)d_in[7];
    const float* gb = (const float*)d_in[8];
    const float* thw = (const float*)d_in[9];
    const float* thb = (const float*)d_in[10];
    const float* phw = (const float*)d_in[11];
    const float* phb = (const float*)d_in[12];
    const float* www = (const float*)d_in[13];
    const float* wwb = (const float*)d_in[14];
    float* out = (float*)d_out;

    float *p_y1, *p_y2c, *p_y3, *p_am, *p_g, *p_y2a;
    __half *p_th, *p_ph, *p_g2t;
    cudaGetSymbolAddress((void**)&p_y1, g_y1);
    cudaGetSymbolAddress((void**)&p_y2c, g_y2c);
    cudaGetSymbolAddress((void**)&p_y3, g_y3);
    cudaGetSymbolAddress((void**)&p_am, g_am);
    cudaGetSymbolAddress((void**)&p_th, g_thh);
    cudaGetSymbolAddress((void**)&p_ph, g_phh);
    cudaGetSymbolAddress((void**)&p_g, g_g);
    cudaGetSymbolAddress((void**)&p_g2t, g_g2t);
    cudaGetSymbolAddress((void**)&p_y2a, g_y2a);

    conv3x3_s2<32, 8><<<128, 256>>>(x, p_y1, d1w, d1b, 64, 32, 1);
    conv3x3_s2<16, 4><<<64, 256>>>(p_y1, p_y2c, d2w, d2b, 32, 16, 1);
    conv3x3_s2<8, 2><<<32, 256>>>(p_y2c, p_y3, d3w, d3b, 16, 8, 0);
    amproj<<<256, 384>>>(p_y3, x, thw, thb, phw, phb, gw, gb, p_am, p_th, p_ph, p_g);
    attn_pass1<<<dim3(64, 4), 128>>>(p_th, p_ph, p_g, p_g2t);
    attn_pass2<<<dim3(64, 4), 128>>>(p_th, p_ph, p_g2t, p_y2a);
    epilogue<<<256, 256>>>(p_y2a, www, wwb, p_am, x, out);
}